// round 12
// baseline (speedup 1.0000x reference)
#include <cuda_runtime.h>
#include <cuda_fp16.h>
#include <cfloat>
#include <math.h>
#include <stdint.h>

// ---------------------------------------------------------------------------
// Problem constants
// ---------------------------------------------------------------------------
#define BATCH 16
#define NMAX  1024
#define EMAX  16384
#define DIM   512
// ns = {1024, 820, 656}, ks = {820, 656, 525}

// ---------------------------------------------------------------------------
// Device scratch (static; no cudaMalloc allowed)
// ---------------------------------------------------------------------------
__device__ float d_hb [BATCH * NMAX * DIM];     // raw gemm outputs (h / x_new)

// fp16 hi/lo operand planes (row-major, K contiguous, stride DIM)
__device__ __half d_x0h[BATCH * NMAX * DIM];    // input x split
__device__ __half d_x0l[BATCH * NMAX * DIM];
__device__ __half d_xbh[BATCH * NMAX * DIM];    // pooled split
__device__ __half d_xbl[BATCH * NMAX * DIM];
__device__ __half d_agh[BATCH * NMAX * DIM];    // aggregated split
__device__ __half d_agl[BATCH * NMAX * DIM];

__device__ __half d_wlh[3 * DIM * DIM];         // c_lin_W split
__device__ __half d_wll[3 * DIM * DIM];
__device__ __half d_wuh[3 * DIM * 2 * DIM];     // c_upd_W split
__device__ __half d_wul[3 * DIM * 2 * DIM];

__device__ int   d_srcA[BATCH * EMAX];
__device__ int   d_dstA[BATCH * EMAX];
__device__ int   d_srcB[BATCH * EMAX];
__device__ int   d_dstB[BATCH * EMAX];

__device__ int   d_off [BATCH * (NMAX + 1)];
__device__ int   d_csr [BATCH * EMAX];

__device__ float d_score[BATCH * NMAX];
__device__ int   d_perm [BATCH * NMAX];
__device__ float d_tanhv[BATCH * NMAX];
__device__ int   d_newidx[BATCH * NMAX];

__device__ float d_z[BATCH * 2 * DIM];
__device__ float d_norms[4];

__device__ __forceinline__ const int* esrc(int sel) { return sel ? d_srcB : d_srcA; }
__device__ __forceinline__ const int* edst(int sel) { return sel ? d_dstB : d_dstA; }
__device__ __forceinline__ int* esrc_w(int sel) { return sel ? d_srcB : d_srcA; }
__device__ __forceinline__ int* edst_w(int sel) { return sel ? d_dstB : d_dstA; }

// ---------------------------------------------------------------------------
// fp16 helpers
// ---------------------------------------------------------------------------
__device__ __forceinline__ void split4h(float4 v, uint2& h, uint2& l) {
    __half hx = __float2half(v.x), hy = __float2half(v.y);
    __half hz = __float2half(v.z), hw = __float2half(v.w);
    __half lx = __float2half(v.x - __half2float(hx));
    __half ly = __float2half(v.y - __half2float(hy));
    __half lz = __float2half(v.z - __half2float(hz));
    __half lw = __float2half(v.w - __half2float(hw));
    h.x = ((uint32_t)__half_as_ushort(hy) << 16) | __half_as_ushort(hx);
    h.y = ((uint32_t)__half_as_ushort(hw) << 16) | __half_as_ushort(hz);
    l.x = ((uint32_t)__half_as_ushort(ly) << 16) | __half_as_ushort(lx);
    l.y = ((uint32_t)__half_as_ushort(lw) << 16) | __half_as_ushort(lz);
}

__device__ __forceinline__ void mma_h16(float* c, const uint32_t* a, const uint32_t* b) {
    asm volatile(
        "mma.sync.aligned.m16n8k16.row.col.f32.f16.f16.f32 "
        "{%0,%1,%2,%3}, {%4,%5,%6,%7}, {%8,%9}, {%0,%1,%2,%3};"
        : "+f"(c[0]), "+f"(c[1]), "+f"(c[2]), "+f"(c[3])
        : "r"(a[0]), "r"(a[1]), "r"(a[2]), "r"(a[3]), "r"(b[0]), "r"(b[1]));
}

__device__ __forceinline__ void ldsm4(uint32_t* r, uint32_t a) {
    asm volatile("ldmatrix.sync.aligned.m8n8.x4.shared.b16 {%0,%1,%2,%3}, [%4];"
                 : "=r"(r[0]), "=r"(r[1]), "=r"(r[2]), "=r"(r[3]) : "r"(a));
}

__device__ __forceinline__ void cpasync16(uint32_t dst, const void* src, int szbytes) {
    asm volatile("cp.async.cg.shared.global [%0], [%1], 16, %2;"
                 :: "r"(dst), "l"(src), "r"(szbytes));
}
__device__ __forceinline__ void cpasync_commit() {
    asm volatile("cp.async.commit_group;");
}
template <int N>
__device__ __forceinline__ void cpasync_wait() {
    asm volatile("cp.async.wait_group %0;" :: "n"(N));
}

// ---------------------------------------------------------------------------
// Init / split kernels
// ---------------------------------------------------------------------------
__global__ void init_edges_kernel(const int* __restrict__ ei) {
    int b = blockIdx.y;
    int e = blockIdx.x * blockDim.x + threadIdx.x;
    if (e < EMAX) {
        d_srcA[b * EMAX + e] = ei[(size_t)b * 2 * EMAX + e];
        d_dstA[b * EMAX + e] = ei[(size_t)b * 2 * EMAX + EMAX + e];
    }
}

__global__ void zero_score_kernel() {
    int i = blockIdx.x * blockDim.x + threadIdx.x;
    if (i < BATCH * NMAX) d_score[i] = 0.f;
}

__global__ void norms_kernel(const float* __restrict__ pw) {
    int l = blockIdx.x;
    int t = threadIdx.x;
    __shared__ float red[256];
    float s = 0.f;
    for (int j = t; j < DIM; j += 256) {
        float v = pw[l * DIM + j];
        s = fmaf(v, v, s);
    }
    red[t] = s;
    __syncthreads();
    for (int o = 128; o > 0; o >>= 1) {
        if (t < o) red[t] += red[t + o];
        __syncthreads();
    }
    if (t == 0) d_norms[l] = 1.0f / sqrtf(red[0]);
}

// dsel: 0 -> x0, 1 -> wl, 2 -> wu   (flat elementwise, float4 granules)
__global__ void split_kernel(const float* __restrict__ src, int dsel, int n4) {
    int i = blockIdx.x * blockDim.x + threadIdx.x;
    if (i >= n4) return;
    __half* H = (dsel == 0) ? d_x0h : (dsel == 1) ? d_wlh : d_wuh;
    __half* L = (dsel == 0) ? d_x0l : (dsel == 1) ? d_wll : d_wul;
    float4 v = ((const float4*)src)[i];
    uint2 h, l;
    split4h(v, h, l);
    ((uint2*)H)[i] = h;
    ((uint2*)L)[i] = l;
}

// ---------------------------------------------------------------------------
// 3xFP16 tensor-core GEMM, BM=128 x BN=256, BK=16, 3-stage cp.async pipeline,
// ldmatrix fragment loads. 256 threads = 8 warps (2x4), warp tile 64x64.
//   C[M,512] = act(A[M,K] @ W[512,K]^T + bias)
//   If pw != nullptr: fused score partials into d_score (quad-reduced atomics).
//   asel: 0 A=x0 (K=512), 1 A=xb (K=512), 2 A=[agg|x0] (K=1024), 3 A=[agg|xb]
// ---------------------------------------------------------------------------
#define PITCH_H 24                         // halves per smem row (16 data + 8 pad)
#define A_PLANE_B (128 * PITCH_H * 2)      // 6144 bytes
#define B_PLANE_B (256 * PITCH_H * 2)      // 12288 bytes
#define OFF_AH 0
#define OFF_AL A_PLANE_B
#define OFF_BH (2 * A_PLANE_B)
#define OFF_BL (2 * A_PLANE_B + B_PLANE_B)
#define STAGE_B (2 * A_PLANE_B + 2 * B_PLANE_B)   // 36864
#define GSMEM_BYTES (3 * STAGE_B)                 // 110592

__global__ void __launch_bounds__(256) gemm_h3_kernel(
    int asel, int layer,
    const float* __restrict__ bias,   // may be nullptr
    const float* __restrict__ pw,     // pool_w row for score fusion, or nullptr
    int M)
{
    extern __shared__ __align__(16) char gsm[];

    const int b  = blockIdx.z;
    const int Kw = (asel >= 2) ? (2 * DIM) : DIM;
    const int nch = Kw >> 4;

    const __half* AxH = ((asel == 0 || asel == 2) ? d_x0h : d_xbh) + (size_t)b * NMAX * DIM;
    const __half* AxL = ((asel == 0 || asel == 2) ? d_x0l : d_xbl) + (size_t)b * NMAX * DIM;
    const __half* AgH = d_agh + (size_t)b * NMAX * DIM;
    const __half* AgL = d_agl + (size_t)b * NMAX * DIM;
    const __half* Wh = (asel >= 2) ? (d_wuh + (size_t)layer * DIM * 2 * DIM)
                                   : (d_wlh + (size_t)layer * DIM * DIM);
    const __half* Wl = (asel >= 2) ? (d_wul + (size_t)layer * DIM * 2 * DIM)
                                   : (d_wll + (size_t)layer * DIM * DIM);
    float* C = d_hb + (size_t)b * NMAX * DIM;

    const int tid  = threadIdx.x;
    const int brow = blockIdx.y * 128;
    const int bcol = blockIdx.x * 256;

    const int warp = tid >> 5;
    const int lane = tid & 31;
    const int wm   = warp & 1;    // 0..1: 64 rows each
    const int wn   = warp >> 1;   // 0..3: 64 cols each
    const int quad = lane >> 2;
    const int tq   = lane & 3;

    // gmem->smem copy mapping: A one 16B granule/thread/plane, B two.
    const int lr = tid >> 1;          // 0..127
    const int hh = (tid & 1) * 8;
    int arow = brow + lr; if (arow >= M) arow = M - 1;
    const int avalid = (brow + lr) < M ? 16 : 0;

    const uint32_t base = (uint32_t)__cvta_generic_to_shared(gsm);
    const uint32_t offA = (uint32_t)(lr * PITCH_H + hh) * 2;   // within A plane
    // B granule g: row = g>>1, hoff = (g&1)*8 ; thread covers g=tid, g=tid+256
    const int br0 = tid >> 1,  bh0 = (tid & 1) * 8;
    const int br1 = 128 + br0, bh1 = bh0;
    const uint32_t offB0 = (uint32_t)(br0 * PITCH_H + bh0) * 2;
    const uint32_t offB1 = (uint32_t)(br1 * PITCH_H + bh1) * 2;

    // ldmatrix per-lane offsets (bytes within a plane)
    const int lr8 = lane & 7, g = lane >> 3;
    const uint32_t oA = (uint32_t)((wm * 64 + (g & 1) * 8 + lr8) * PITCH_H + (g >> 1) * 8) * 2;
    const uint32_t oB = (uint32_t)((wn * 64 + (g >> 1) * 8 + lr8) * PITCH_H + (g & 1) * 8) * 2;

    float acc[4][8][4];
#pragma unroll
    for (int i = 0; i < 4; i++)
#pragma unroll
        for (int j = 0; j < 8; j++)
#pragma unroll
            for (int e = 0; e < 4; e++) acc[i][j][e] = 0.f;

    auto cp_chunk = [&](int c, int stage) {
        const int k0 = c << 4;
        const __half* aH; const __half* aL; int ko = k0;
        if (asel < 2 || k0 < DIM) {
            if (asel >= 2) { aH = AgH; aL = AgL; }
            else           { aH = AxH; aL = AxL; }
        } else {
            aH = AxH; aL = AxL; ko = k0 - DIM;
        }
        const uint32_t sb = base + (uint32_t)(stage * STAGE_B);
        cpasync16(sb + OFF_AH + offA, aH + (size_t)arow * DIM + ko + hh, avalid);
        cpasync16(sb + OFF_AL + offA, aL + (size_t)arow * DIM + ko + hh, avalid);
        cpasync16(sb + OFF_BH + offB0, Wh + (size_t)(bcol + br0) * Kw + k0 + bh0, 16);
        cpasync16(sb + OFF_BH + offB1, Wh + (size_t)(bcol + br1) * Kw + k0 + bh1, 16);
        cpasync16(sb + OFF_BL + offB0, Wl + (size_t)(bcol + br0) * Kw + k0 + bh0, 16);
        cpasync16(sb + OFF_BL + offB1, Wl + (size_t)(bcol + br1) * Kw + k0 + bh1, 16);
        cpasync_commit();
    };

    cp_chunk(0, 0);
    cp_chunk(1, 1);

    for (int c = 0; c < nch; c++) {
        if (c == nch - 1) cpasync_wait<0>();
        else              cpasync_wait<1>();
        __syncthreads();
        if (c + 2 < nch) cp_chunk(c + 2, (c + 2) % 3);

        const uint32_t sb = base + (uint32_t)((c % 3) * STAGE_B);

        uint32_t ah[4][4], al[4][4];
#pragma unroll
        for (int mi = 0; mi < 4; mi++) {
            ldsm4(ah[mi], sb + OFF_AH + oA + mi * (16 * PITCH_H * 2));
            ldsm4(al[mi], sb + OFF_AL + oA + mi * (16 * PITCH_H * 2));
        }
        // stream B fragments 2 n-tiles at a time (keeps live regs low)
#pragma unroll
        for (int i = 0; i < 4; i++) {
            uint32_t bh2[4], bl2[4];   // [2 tiles][2 k-halves]
            ldsm4(bh2, sb + OFF_BH + oB + i * (16 * PITCH_H * 2));
            ldsm4(bl2, sb + OFF_BL + oB + i * (16 * PITCH_H * 2));
#pragma unroll
            for (int mi = 0; mi < 4; mi++) {
#pragma unroll
                for (int nj = 0; nj < 2; nj++) {
                    float* a = acc[mi][2 * i + nj];
                    mma_h16(a, al[mi], bh2 + 2 * nj);
                    mma_h16(a, ah[mi], bl2 + 2 * nj);
                    mma_h16(a, ah[mi], bh2 + 2 * nj);
                }
            }
        }
    }

    // epilogue: bias + relu (+ fused score partials)
    float wv[8][2];
    if (pw) {
#pragma unroll
        for (int ni = 0; ni < 8; ni++) {
            const int c0 = bcol + wn * 64 + ni * 8 + 2 * tq;
            wv[ni][0] = pw[c0];
            wv[ni][1] = pw[c0 + 1];
        }
    }

#pragma unroll
    for (int mi = 0; mi < 4; mi++) {
        const int r0 = brow + wm * 64 + mi * 16 + quad;
        float sc0 = 0.f, sc1 = 0.f;
#pragma unroll
        for (int ni = 0; ni < 8; ni++) {
            const int c0 = bcol + wn * 64 + ni * 8 + 2 * tq;
            float bv0 = 0.f, bv1 = 0.f;
            if (bias) { bv0 = bias[c0]; bv1 = bias[c0 + 1]; }
            float v0x = fmaxf(acc[mi][ni][0] + bv0, 0.f);
            float v0y = fmaxf(acc[mi][ni][1] + bv1, 0.f);
            float v1x = fmaxf(acc[mi][ni][2] + bv0, 0.f);
            float v1y = fmaxf(acc[mi][ni][3] + bv1, 0.f);
            if (r0 < M)     *(float2*)(C + (size_t)r0 * DIM + c0) = make_float2(v0x, v0y);
            if (r0 + 8 < M) *(float2*)(C + (size_t)(r0 + 8) * DIM + c0) = make_float2(v1x, v1y);
            if (pw) {
                sc0 = fmaf(v0x, wv[ni][0], fmaf(v0y, wv[ni][1], sc0));
                sc1 = fmaf(v1x, wv[ni][0], fmaf(v1y, wv[ni][1], sc1));
            }
        }
        if (pw) {
            sc0 += __shfl_xor_sync(0xffffffffu, sc0, 1);
            sc0 += __shfl_xor_sync(0xffffffffu, sc0, 2);
            sc1 += __shfl_xor_sync(0xffffffffu, sc1, 1);
            sc1 += __shfl_xor_sync(0xffffffffu, sc1, 2);
            if (tq == 0) {
                if (r0 < M)     atomicAdd(&d_score[b * NMAX + r0], sc0);
                if (r0 + 8 < M) atomicAdd(&d_score[b * NMAX + r0 + 8], sc1);
            }
        }
    }
}

// ---------------------------------------------------------------------------
// Fused CSR build
// ---------------------------------------------------------------------------
__global__ void __launch_bounds__(1024) build_csr_kernel(int sel) {
    __shared__ int sh[NMAX];
    __shared__ int cur[NMAX];
    const int b = blockIdx.x, t = threadIdx.x;

    sh[t] = 0;
    __syncthreads();

    const int* S = esrc(sel) + b * EMAX;
    const int* D = edst(sel) + b * EMAX;

#pragma unroll 4
    for (int e = t; e < EMAX; e += 1024) {
        int s = S[e], d = D[e];
        if (s >= 0 && s != d) atomicAdd(&sh[d], 1);
    }
    __syncthreads();

    int v = sh[t];
    for (int off = 1; off < NMAX; off <<= 1) {
        int add = (t >= off) ? sh[t - off] : 0;
        __syncthreads();
        sh[t] += add;
        __syncthreads();
    }
    int excl = sh[t] - v;
    d_off[b * (NMAX + 1) + t] = excl;
    cur[t] = excl;
    if (t == NMAX - 1) d_off[b * (NMAX + 1) + NMAX] = sh[t];
    __syncthreads();

#pragma unroll 4
    for (int e = t; e < EMAX; e += 1024) {
        int s = S[e], d = D[e];
        if (s >= 0 && s != d) {
            int pos = atomicAdd(&cur[d], 1);
            d_csr[b * EMAX + pos] = s;
        }
    }
}

// ---------------------------------------------------------------------------
// Aggregation: agg[i] = h[i] + sum_{j->i} h[j], split to fp16 planes.
// ---------------------------------------------------------------------------
__global__ void __launch_bounds__(128) agg_split_kernel(int n) {
    int b = blockIdx.y, i = blockIdx.x;
    if (i >= n) return;
    int t = threadIdx.x;
    size_t row = (size_t)(b * NMAX + i);

    float4 acc = ((const float4*)(d_hb + row * DIM))[t];
    float4 acc2 = make_float4(0.f, 0.f, 0.f, 0.f);
    int beg = d_off[b * (NMAX + 1) + i];
    int end = d_off[b * (NMAX + 1) + i + 1];
    int e = beg;
    for (; e + 1 < end; e += 2) {
        int s0 = d_csr[b * EMAX + e];
        int s1 = d_csr[b * EMAX + e + 1];
        float4 v0 = ((const float4*)(d_hb + (size_t)(b * NMAX + s0) * DIM))[t];
        float4 v1 = ((const float4*)(d_hb + (size_t)(b * NMAX + s1) * DIM))[t];
        acc.x += v0.x; acc.y += v0.y; acc.z += v0.z; acc.w += v0.w;
        acc2.x += v1.x; acc2.y += v1.y; acc2.z += v1.z; acc2.w += v1.w;
    }
    if (e < end) {
        int s0 = d_csr[b * EMAX + e];
        float4 v0 = ((const float4*)(d_hb + (size_t)(b * NMAX + s0) * DIM))[t];
        acc.x += v0.x; acc.y += v0.y; acc.z += v0.z; acc.w += v0.w;
    }
    acc.x += acc2.x; acc.y += acc2.y; acc.z += acc2.z; acc.w += acc2.w;

    uint2 h, l;
    split4h(acc, h, l);
    ((uint2*)(d_agh + row * DIM))[t] = h;
    ((uint2*)(d_agl + row * DIM))[t] = l;
}

// ---------------------------------------------------------------------------
// Top-k via bitonic sort (tie-break: lower index wins) + fused edge remap.
// ---------------------------------------------------------------------------
__global__ void __launch_bounds__(512) topk_kernel(int n, int k, int layer,
                                                   int doRemap, int inSel, int outSel) {
    __shared__ float sv[NMAX];
    __shared__ int   si[NMAX];
    int b = blockIdx.x, t = threadIdx.x;
    float inv = d_norms[layer];

    for (int i = t; i < NMAX; i += 512) {
        sv[i] = (i < n) ? d_score[b * NMAX + i] * inv : -FLT_MAX;
        si[i] = i;
        d_score[b * NMAX + i] = 0.f;   // reset for next layer's fused score
    }
    __syncthreads();

    for (int size = 2; size <= NMAX; size <<= 1) {
        for (int stride = size >> 1; stride > 0; stride >>= 1) {
            for (int i = t; i < NMAX; i += 512) {
                int j = i ^ stride;
                if (j > i) {
                    float v1 = sv[i], v2 = sv[j];
                    int   i1 = si[i], i2 = si[j];
                    bool gt = (v1 > v2) || (v1 == v2 && i1 < i2);
                    bool up = ((i & size) == 0);
                    if (up ? gt : !gt) {
                        sv[i] = v2; sv[j] = v1;
                        si[i] = i2; si[j] = i1;
                    }
                }
            }
            __syncthreads();
        }
    }

    for (int i = t; i < NMAX; i += 512) d_newidx[b * NMAX + i] = -1;
    __syncthreads();
    for (int j = t; j < k; j += 512) {
        int   src = si[NMAX - 1 - j];
        float val = sv[NMAX - 1 - j];
        d_perm [b * NMAX + j]    = src;
        d_tanhv[b * NMAX + j]    = tanhf(val);
        d_newidx[b * NMAX + src] = j;
    }

    if (doRemap) {
        __syncthreads();
        const int* S = esrc(inSel) + b * EMAX;
        const int* D = edst(inSel) + b * EMAX;
        int* So = esrc_w(outSel) + b * EMAX;
        int* Do = edst_w(outSel) + b * EMAX;
        for (int e = t; e < EMAX; e += 512) {
            int s = S[e], d = D[e];
            int s2 = -1, d2 = 0;
            if (s >= 0) {
                s2 = d_newidx[b * NMAX + s];
                d2 = d_newidx[b * NMAX + d];
                if (d2 < 0) s2 = -1;
                if (d2 < 0) d2 = 0;
            }
            So[e] = s2;
            Do[e] = (s2 >= 0) ? d2 : 0;
        }
    }
}

// ---------------------------------------------------------------------------
// Gather (layers 0,1 only): xb fp16 planes = split(hb[perm]*tanh)
// ---------------------------------------------------------------------------
__global__ void __launch_bounds__(128) gather_kernel(int k) {
    int b = blockIdx.y, j = blockIdx.x;
    if (j >= k) return;
    int t = threadIdx.x;
    int   p  = d_perm [b * NMAX + j];
    float tv = d_tanhv[b * NMAX + j];
    float4 v = ((const float4*)(d_hb + (size_t)(b * NMAX + p) * DIM))[t];
    v.x *= tv; v.y *= tv; v.z *= tv; v.w *= tv;
    uint2 h, l;
    split4h(v, h, l);
    ((uint2*)(d_xbh + (size_t)(b * NMAX + j) * DIM))[t] = h;
    ((uint2*)(d_xbl + (size_t)(b * NMAX + j) * DIM))[t] = l;
}

// ---------------------------------------------------------------------------
// Readout: z[b,0:512] (+)= max_j hb[perm[j]]*tanh; z[b,512:] (+)= mean
// ---------------------------------------------------------------------------
__global__ void readout_kernel(int k, int first) {
    int b = blockIdx.y;
    int f = blockIdx.x * 256 + threadIdx.x;
    const float* H  = d_hb + (size_t)b * NMAX * DIM + f;
    const int*   P  = d_perm  + b * NMAX;
    const float* Tv = d_tanhv + b * NMAX;
    float mx = -FLT_MAX, sm = 0.f;
#pragma unroll 4
    for (int j = 0; j < k; j++) {
        float v = H[(size_t)P[j] * DIM] * Tv[j];
        mx = fmaxf(mx, v);
        sm += v;
    }
    float mean = sm / (float)k;
    if (first) {
        d_z[b * 2 * DIM + f]       = mx;
        d_z[b * 2 * DIM + DIM + f] = mean;
    } else {
        d_z[b * 2 * DIM + f]       += mx;
        d_z[b * 2 * DIM + DIM + f] += mean;
    }
}

// ---------------------------------------------------------------------------
// Final MLP: out = relu(z @ lin1^T + b1) @ lin2^T + b2
// ---------------------------------------------------------------------------
__global__ void __launch_bounds__(256) mlp_kernel(
    const float* __restrict__ lin1W, const float* __restrict__ lin1b,
    const float* __restrict__ lin2W, const float* __restrict__ lin2b,
    float* __restrict__ out)
{
    int b = blockIdx.x, t = threadIdx.x;
    int warp = t >> 5, lane = t & 31;
    __shared__ float zsh[2 * DIM];
    __shared__ float y1[DIM];

    for (int i = t; i < 2 * DIM; i += 256) zsh[i] = d_z[b * 2 * DIM + i];
    __syncthreads();

    for (int o = warp * 64; o < warp * 64 + 64; o++) {
        const float* wr = lin1W + (size_t)o * 2 * DIM;
        float s = 0.f;
        for (int j = lane; j < 2 * DIM; j += 32) s = fmaf(zsh[j], wr[j], s);
#pragma unroll
        for (int off = 16; off > 0; off >>= 1) s += __shfl_xor_sync(0xffffffffu, s, off);
        if (lane == 0) y1[o] = fmaxf(s + lin1b[o], 0.f);
    }
    __syncthreads();

    for (int o = warp * 32; o < warp * 32 + 32; o++) {
        const float* wr = lin2W + (size_t)o * DIM;
        float s = 0.f;
        for (int j = lane; j < DIM; j += 32) s = fmaf(y1[j], wr[j], s);
#pragma unroll
        for (int off = 16; off > 0; off >>= 1) s += __shfl_xor_sync(0xffffffffu, s, off);
        if (lane == 0) out[b * 256 + o] = s + lin2b[o];
    }
}

// ---------------------------------------------------------------------------
// Host launcher — kernel launches + one device-attribute set (capture-safe)
// ---------------------------------------------------------------------------
extern "C" void kernel_launch(void* const* d_in, const int* in_sizes, int n_in,
                              void* d_out, int out_size)
{
    const float* x       = (const float*)d_in[0];
    const int*   ei      = (const int*)  d_in[1];
    const float* c_lin_W = (const float*)d_in[2];
    const float* c_lin_b = (const float*)d_in[3];
    const float* c_upd_W = (const float*)d_in[4];
    const float* pool_w  = (const float*)d_in[5];
    const float* lin1_W  = (const float*)d_in[6];
    const float* lin1_b  = (const float*)d_in[7];
    const float* lin2_W  = (const float*)d_in[8];
    const float* lin2_b  = (const float*)d_in[9];
    float* out = (float*)d_out;

    cudaFuncSetAttribute(gemm_h3_kernel,
                         cudaFuncAttributeMaxDynamicSharedMemorySize, GSMEM_BYTES);

    const int ns[3] = {1024, 820, 656};
    const int ks[3] = {820, 656, 525};

    init_edges_kernel<<<dim3(EMAX / 256, BATCH), 256>>>(ei);
    zero_score_kernel<<<(BATCH * NMAX + 255) / 256, 256>>>();
    norms_kernel<<<3, 256>>>(pool_w);

    // pre-split x and weights into fp16 hi/lo planes
    {
        int nx = BATCH * NMAX * DIM / 4;
        split_kernel<<<(nx + 255) / 256, 256>>>(x, 0, nx);
        int nl = 3 * DIM * DIM / 4;
        split_kernel<<<(nl + 255) / 256, 256>>>(c_lin_W, 1, nl);
        int nu = 3 * DIM * 2 * DIM / 4;
        split_kernel<<<(nu + 255) / 256, 256>>>(c_upd_W, 2, nu);
    }

    for (int l = 0; l < 3; l++) {
        int n = ns[l], k = ks[l];
        int inSel = l & 1;
        int outSel = inSel ^ 1;
        int xsel = (l == 0) ? 0 : 1;
        int nrow = (n + 127) / 128;

        // h = relu(x @ Wl^T + bl)
        gemm_h3_kernel<<<dim3(DIM / 256, nrow, BATCH), 256, GSMEM_BYTES>>>(
            xsel, l, c_lin_b + l * DIM, nullptr, n);

        build_csr_kernel<<<BATCH, 1024>>>(inSel);

        agg_split_kernel<<<dim3(n, BATCH), 128>>>(n);

        // x_new = relu([agg|x] @ Wu^T)  (+ fused raw score partials)
        gemm_h3_kernel<<<dim3(DIM / 256, nrow, BATCH), 256, GSMEM_BYTES>>>(
            2 + xsel, l, nullptr, pool_w + l * DIM, n);

        // top-k (+ normalized score, tanh, newidx) + fused edge remap
        topk_kernel<<<BATCH, 512>>>(n, k, l, l < 2 ? 1 : 0, inSel, outSel);

        if (l < 2)
            gather_kernel<<<dim3(k, BATCH), 128>>>(k);

        readout_kernel<<<dim3(DIM / 256, BATCH), 256>>>(k, l == 0 ? 1 : 0);
    }

    mlp_kernel<<<BATCH, 256>>>(lin1_W, lin1_b, lin2_W, lin2_b, out);
}

// round 13
// speedup vs baseline: 1.2798x; 1.2798x over previous
#include <cuda_runtime.h>
#include <cuda_fp16.h>
#include <cfloat>
#include <math.h>
#include <stdint.h>

// ---------------------------------------------------------------------------
// Problem constants
// ---------------------------------------------------------------------------
#define BATCH 16
#define NMAX  1024
#define EMAX  16384
#define DIM   512
// ns = {1024, 820, 656}, ks = {820, 656, 525}

// ---------------------------------------------------------------------------
// Device scratch (static; no cudaMalloc allowed)
// ---------------------------------------------------------------------------
__device__ float d_hb [BATCH * NMAX * DIM];     // raw gemm outputs (h / x_new)

// fp16 hi/lo operand planes (row-major, K contiguous, stride DIM)
__device__ __half d_x0h[BATCH * NMAX * DIM];    // input x split
__device__ __half d_x0l[BATCH * NMAX * DIM];
__device__ __half d_xbh[BATCH * NMAX * DIM];    // pooled split
__device__ __half d_xbl[BATCH * NMAX * DIM];
__device__ __half d_agh[BATCH * NMAX * DIM];    // aggregated split
__device__ __half d_agl[BATCH * NMAX * DIM];

__device__ __half d_wlh[3 * DIM * DIM];         // c_lin_W split
__device__ __half d_wll[3 * DIM * DIM];
__device__ __half d_wuh[3 * DIM * 2 * DIM];     // c_upd_W split
__device__ __half d_wul[3 * DIM * 2 * DIM];

__device__ int   d_srcA[BATCH * EMAX];
__device__ int   d_dstA[BATCH * EMAX];
__device__ int   d_srcB[BATCH * EMAX];
__device__ int   d_dstB[BATCH * EMAX];

__device__ int   d_off [BATCH * (NMAX + 1)];
__device__ int   d_csr [BATCH * EMAX];

__device__ float d_score[BATCH * NMAX];
__device__ int   d_perm [BATCH * NMAX];
__device__ float d_tanhv[BATCH * NMAX];
__device__ int   d_newidx[BATCH * NMAX];

// readout partials: [jchunk][batch][512] for max and sum
#define RJC 8
__device__ float d_rmax[RJC * BATCH * DIM];
__device__ float d_rsum[RJC * BATCH * DIM];

__device__ float d_z[BATCH * 2 * DIM];
__device__ float d_norms[4];

__device__ __forceinline__ const int* esrc(int sel) { return sel ? d_srcB : d_srcA; }
__device__ __forceinline__ const int* edst(int sel) { return sel ? d_dstB : d_dstA; }
__device__ __forceinline__ int* esrc_w(int sel) { return sel ? d_srcB : d_srcA; }
__device__ __forceinline__ int* edst_w(int sel) { return sel ? d_dstB : d_dstA; }

// ---------------------------------------------------------------------------
// fp16 helpers
// ---------------------------------------------------------------------------
__device__ __forceinline__ void split4h(float4 v, uint2& h, uint2& l) {
    __half hx = __float2half(v.x), hy = __float2half(v.y);
    __half hz = __float2half(v.z), hw = __float2half(v.w);
    __half lx = __float2half(v.x - __half2float(hx));
    __half ly = __float2half(v.y - __half2float(hy));
    __half lz = __float2half(v.z - __half2float(hz));
    __half lw = __float2half(v.w - __half2float(hw));
    h.x = ((uint32_t)__half_as_ushort(hy) << 16) | __half_as_ushort(hx);
    h.y = ((uint32_t)__half_as_ushort(hw) << 16) | __half_as_ushort(hz);
    l.x = ((uint32_t)__half_as_ushort(ly) << 16) | __half_as_ushort(lx);
    l.y = ((uint32_t)__half_as_ushort(lw) << 16) | __half_as_ushort(lz);
}

__device__ __forceinline__ void mma_h16(float* c, const uint32_t* a, const uint32_t* b) {
    asm volatile(
        "mma.sync.aligned.m16n8k16.row.col.f32.f16.f16.f32 "
        "{%0,%1,%2,%3}, {%4,%5,%6,%7}, {%8,%9}, {%0,%1,%2,%3};"
        : "+f"(c[0]), "+f"(c[1]), "+f"(c[2]), "+f"(c[3])
        : "r"(a[0]), "r"(a[1]), "r"(a[2]), "r"(a[3]), "r"(b[0]), "r"(b[1]));
}

__device__ __forceinline__ void ldsm4(uint32_t* r, uint32_t a) {
    asm volatile("ldmatrix.sync.aligned.m8n8.x4.shared.b16 {%0,%1,%2,%3}, [%4];"
                 : "=r"(r[0]), "=r"(r[1]), "=r"(r[2]), "=r"(r[3]) : "r"(a));
}

__device__ __forceinline__ void cpasync16(uint32_t dst, const void* src, int szbytes) {
    asm volatile("cp.async.cg.shared.global [%0], [%1], 16, %2;"
                 :: "r"(dst), "l"(src), "r"(szbytes));
}
__device__ __forceinline__ void cpasync_commit() {
    asm volatile("cp.async.commit_group;");
}
template <int N>
__device__ __forceinline__ void cpasync_wait() {
    asm volatile("cp.async.wait_group %0;" :: "n"(N));
}

// ---------------------------------------------------------------------------
// Init / split kernels
// ---------------------------------------------------------------------------
__global__ void init_edges_kernel(const int* __restrict__ ei) {
    int b = blockIdx.y;
    int e = blockIdx.x * blockDim.x + threadIdx.x;
    if (e < EMAX) {
        d_srcA[b * EMAX + e] = ei[(size_t)b * 2 * EMAX + e];
        d_dstA[b * EMAX + e] = ei[(size_t)b * 2 * EMAX + EMAX + e];
    }
}

__global__ void zero_score_kernel() {
    int i = blockIdx.x * blockDim.x + threadIdx.x;
    if (i < BATCH * NMAX) d_score[i] = 0.f;
}

__global__ void norms_kernel(const float* __restrict__ pw) {
    int l = blockIdx.x;
    int t = threadIdx.x;
    __shared__ float red[256];
    float s = 0.f;
    for (int j = t; j < DIM; j += 256) {
        float v = pw[l * DIM + j];
        s = fmaf(v, v, s);
    }
    red[t] = s;
    __syncthreads();
    for (int o = 128; o > 0; o >>= 1) {
        if (t < o) red[t] += red[t + o];
        __syncthreads();
    }
    if (t == 0) d_norms[l] = 1.0f / sqrtf(red[0]);
}

// dsel: 0 -> x0, 1 -> wl, 2 -> wu   (flat elementwise, float4 granules)
__global__ void split_kernel(const float* __restrict__ src, int dsel, int n4) {
    int i = blockIdx.x * blockDim.x + threadIdx.x;
    if (i >= n4) return;
    __half* H = (dsel == 0) ? d_x0h : (dsel == 1) ? d_wlh : d_wuh;
    __half* L = (dsel == 0) ? d_x0l : (dsel == 1) ? d_wll : d_wul;
    float4 v = ((const float4*)src)[i];
    uint2 h, l;
    split4h(v, h, l);
    ((uint2*)H)[i] = h;
    ((uint2*)L)[i] = l;
}

// ---------------------------------------------------------------------------
// 3xFP16 tensor-core GEMM (R11 config: BM=128 BN=128 BK=16, 3-stage, ldmatrix)
//   C[M,512] = act(A[M,K] @ W[512,K]^T + bias)
//   If pw != nullptr: fused score partials into d_score.
//   asel: 0 A=x0 (K=512), 1 A=xb (K=512), 2 A=[agg|x0] (K=1024), 3 A=[agg|xb]
// ---------------------------------------------------------------------------
#define PITCH_H 24
#define TILE_H  (128 * PITCH_H)
#define TILE_B  (TILE_H * 2)
#define GSMEM_BYTES (4 * 3 * TILE_B)   // 73728

__global__ void __launch_bounds__(256, 2) gemm_h3_kernel(
    int asel, int layer,
    const float* __restrict__ bias,
    const float* __restrict__ pw,
    int M)
{
    extern __shared__ __align__(16) __half gsm[];
    __half* AsH = gsm;
    __half* AsL = gsm + 3 * TILE_H;
    __half* BsH = gsm + 6 * TILE_H;
    __half* BsL = gsm + 9 * TILE_H;

    const int b  = blockIdx.z;
    const int Kw = (asel >= 2) ? (2 * DIM) : DIM;
    const int nch = Kw >> 4;

    const __half* AxH = ((asel == 0 || asel == 2) ? d_x0h : d_xbh) + (size_t)b * NMAX * DIM;
    const __half* AxL = ((asel == 0 || asel == 2) ? d_x0l : d_xbl) + (size_t)b * NMAX * DIM;
    const __half* AgH = d_agh + (size_t)b * NMAX * DIM;
    const __half* AgL = d_agl + (size_t)b * NMAX * DIM;
    const __half* Wh = (asel >= 2) ? (d_wuh + (size_t)layer * DIM * 2 * DIM)
                                   : (d_wlh + (size_t)layer * DIM * DIM);
    const __half* Wl = (asel >= 2) ? (d_wul + (size_t)layer * DIM * 2 * DIM)
                                   : (d_wll + (size_t)layer * DIM * DIM);
    float* C = d_hb + (size_t)b * NMAX * DIM;

    const int tid  = threadIdx.x;
    const int brow = blockIdx.y * 128;
    const int bcol = blockIdx.x * 128;

    const int warp = tid >> 5;
    const int lane = tid & 31;
    const int wm   = warp & 1;
    const int wn   = warp >> 1;
    const int quad = lane >> 2;
    const int tq   = lane & 3;

    const int lr = tid >> 1;
    const int hh = (tid & 1) * 8;
    int arow = brow + lr; if (arow >= M) arow = M - 1;
    const int avalid = (brow + lr) < M ? 16 : 0;

    const uint32_t baseAh = (uint32_t)__cvta_generic_to_shared(AsH);
    const uint32_t baseAl = (uint32_t)__cvta_generic_to_shared(AsL);
    const uint32_t baseBh = (uint32_t)__cvta_generic_to_shared(BsH);
    const uint32_t baseBl = (uint32_t)__cvta_generic_to_shared(BsL);
    const uint32_t offCp = (uint32_t)(lr * PITCH_H + hh) * 2;

    const int lr8 = lane & 7, g = lane >> 3;
    const uint32_t oA = (uint32_t)((wm * 64 + (g & 1) * 8 + lr8) * PITCH_H + (g >> 1) * 8) * 2;
    const uint32_t oB = (uint32_t)((wn * 32 + (g >> 1) * 8 + lr8) * PITCH_H + (g & 1) * 8) * 2;

    float acc[4][4][4];
#pragma unroll
    for (int i = 0; i < 4; i++)
#pragma unroll
        for (int j = 0; j < 4; j++)
#pragma unroll
            for (int e = 0; e < 4; e++) acc[i][j][e] = 0.f;

    auto cp_chunk = [&](int c, int stage) {
        const int k0 = c << 4;
        const __half* aH; const __half* aL; int ko = k0;
        if (asel < 2 || k0 < DIM) {
            if (asel >= 2) { aH = AgH; aL = AgL; }
            else           { aH = AxH; aL = AxL; }
        } else {
            aH = AxH; aL = AxL; ko = k0 - DIM;
        }
        const uint32_t sb = (uint32_t)(stage * TILE_B) + offCp;
        cpasync16(baseAh + sb, aH + (size_t)arow * DIM + ko + hh, avalid);
        cpasync16(baseAl + sb, aL + (size_t)arow * DIM + ko + hh, avalid);
        cpasync16(baseBh + sb, Wh + (size_t)(bcol + lr) * Kw + k0 + hh, 16);
        cpasync16(baseBl + sb, Wl + (size_t)(bcol + lr) * Kw + k0 + hh, 16);
        cpasync_commit();
    };

    cp_chunk(0, 0);
    cp_chunk(1, 1);

    for (int c = 0; c < nch; c++) {
        if (c == nch - 1) cpasync_wait<0>();
        else              cpasync_wait<1>();
        __syncthreads();
        if (c + 2 < nch) cp_chunk(c + 2, (c + 2) % 3);

        const uint32_t sb = (uint32_t)((c % 3) * TILE_B);

        uint32_t ah[4][4], al[4][4];
#pragma unroll
        for (int mi = 0; mi < 4; mi++) {
            ldsm4(ah[mi], baseAh + sb + oA + mi * (16 * PITCH_H * 2));
            ldsm4(al[mi], baseAl + sb + oA + mi * (16 * PITCH_H * 2));
        }
        uint32_t bh[4][2], bl[4][2];
        ldsm4(&bh[0][0], baseBh + sb + oB);
        ldsm4(&bh[2][0], baseBh + sb + oB + 16 * PITCH_H * 2);
        ldsm4(&bl[0][0], baseBl + sb + oB);
        ldsm4(&bl[2][0], baseBl + sb + oB + 16 * PITCH_H * 2);

#pragma unroll
        for (int mi = 0; mi < 4; mi++)
#pragma unroll
            for (int ni = 0; ni < 4; ni++) {
                mma_h16(acc[mi][ni], al[mi], bh[ni]);
                mma_h16(acc[mi][ni], ah[mi], bl[ni]);
                mma_h16(acc[mi][ni], ah[mi], bh[ni]);
            }
    }

    // epilogue: bias + relu (+ fused score partials)
    float wv[4][2];
    if (pw) {
#pragma unroll
        for (int ni = 0; ni < 4; ni++) {
            const int c0 = bcol + wn * 32 + ni * 8 + 2 * tq;
            wv[ni][0] = pw[c0];
            wv[ni][1] = pw[c0 + 1];
        }
    }

#pragma unroll
    for (int mi = 0; mi < 4; mi++) {
        const int r0 = brow + wm * 64 + mi * 16 + quad;
        float sc0 = 0.f, sc1 = 0.f;
#pragma unroll
        for (int ni = 0; ni < 4; ni++) {
            const int c0 = bcol + wn * 32 + ni * 8 + 2 * tq;
            float bv0 = 0.f, bv1 = 0.f;
            if (bias) { bv0 = bias[c0]; bv1 = bias[c0 + 1]; }
            float v0x = fmaxf(acc[mi][ni][0] + bv0, 0.f);
            float v0y = fmaxf(acc[mi][ni][1] + bv1, 0.f);
            float v1x = fmaxf(acc[mi][ni][2] + bv0, 0.f);
            float v1y = fmaxf(acc[mi][ni][3] + bv1, 0.f);
            if (r0 < M)     *(float2*)(C + (size_t)r0 * DIM + c0) = make_float2(v0x, v0y);
            if (r0 + 8 < M) *(float2*)(C + (size_t)(r0 + 8) * DIM + c0) = make_float2(v1x, v1y);
            if (pw) {
                sc0 = fmaf(v0x, wv[ni][0], fmaf(v0y, wv[ni][1], sc0));
                sc1 = fmaf(v1x, wv[ni][0], fmaf(v1y, wv[ni][1], sc1));
            }
        }
        if (pw) {
            sc0 += __shfl_xor_sync(0xffffffffu, sc0, 1);
            sc0 += __shfl_xor_sync(0xffffffffu, sc0, 2);
            sc1 += __shfl_xor_sync(0xffffffffu, sc1, 1);
            sc1 += __shfl_xor_sync(0xffffffffu, sc1, 2);
            if (tq == 0) {
                if (r0 < M)     atomicAdd(&d_score[b * NMAX + r0], sc0);
                if (r0 + 8 < M) atomicAdd(&d_score[b * NMAX + r0 + 8], sc1);
            }
        }
    }
}

// ---------------------------------------------------------------------------
// Fused CSR build
// ---------------------------------------------------------------------------
__global__ void __launch_bounds__(1024) build_csr_kernel(int sel) {
    __shared__ int sh[NMAX];
    __shared__ int cur[NMAX];
    const int b = blockIdx.x, t = threadIdx.x;

    sh[t] = 0;
    __syncthreads();

    const int* S = esrc(sel) + b * EMAX;
    const int* D = edst(sel) + b * EMAX;

#pragma unroll 4
    for (int e = t; e < EMAX; e += 1024) {
        int s = S[e], d = D[e];
        if (s >= 0 && s != d) atomicAdd(&sh[d], 1);
    }
    __syncthreads();

    int v = sh[t];
    for (int off = 1; off < NMAX; off <<= 1) {
        int add = (t >= off) ? sh[t - off] : 0;
        __syncthreads();
        sh[t] += add;
        __syncthreads();
    }
    int excl = sh[t] - v;
    d_off[b * (NMAX + 1) + t] = excl;
    cur[t] = excl;
    if (t == NMAX - 1) d_off[b * (NMAX + 1) + NMAX] = sh[t];
    __syncthreads();

#pragma unroll 4
    for (int e = t; e < EMAX; e += 1024) {
        int s = S[e], d = D[e];
        if (s >= 0 && s != d) {
            int pos = atomicAdd(&cur[d], 1);
            d_csr[b * EMAX + pos] = s;
        }
    }
}

// ---------------------------------------------------------------------------
// Aggregation: agg[i] = h[i] + sum_{j->i} h[j], split to fp16 planes.
// ---------------------------------------------------------------------------
__global__ void __launch_bounds__(128) agg_split_kernel(int n) {
    int b = blockIdx.y, i = blockIdx.x;
    if (i >= n) return;
    int t = threadIdx.x;
    size_t row = (size_t)(b * NMAX + i);

    float4 acc = ((const float4*)(d_hb + row * DIM))[t];
    float4 acc2 = make_float4(0.f, 0.f, 0.f, 0.f);
    int beg = d_off[b * (NMAX + 1) + i];
    int end = d_off[b * (NMAX + 1) + i + 1];
    int e = beg;
    for (; e + 1 < end; e += 2) {
        int s0 = d_csr[b * EMAX + e];
        int s1 = d_csr[b * EMAX + e + 1];
        float4 v0 = ((const float4*)(d_hb + (size_t)(b * NMAX + s0) * DIM))[t];
        float4 v1 = ((const float4*)(d_hb + (size_t)(b * NMAX + s1) * DIM))[t];
        acc.x += v0.x; acc.y += v0.y; acc.z += v0.z; acc.w += v0.w;
        acc2.x += v1.x; acc2.y += v1.y; acc2.z += v1.z; acc2.w += v1.w;
    }
    if (e < end) {
        int s0 = d_csr[b * EMAX + e];
        float4 v0 = ((const float4*)(d_hb + (size_t)(b * NMAX + s0) * DIM))[t];
        acc.x += v0.x; acc.y += v0.y; acc.z += v0.z; acc.w += v0.w;
    }
    acc.x += acc2.x; acc.y += acc2.y; acc.z += acc2.z; acc.w += acc2.w;

    uint2 h, l;
    split4h(acc, h, l);
    ((uint2*)(d_agh + row * DIM))[t] = h;
    ((uint2*)(d_agl + row * DIM))[t] = l;
}

// ---------------------------------------------------------------------------
// Top-k via bitonic sort (tie-break: lower index wins) + fused edge remap.
// ---------------------------------------------------------------------------
__global__ void __launch_bounds__(512) topk_kernel(int n, int k, int layer,
                                                   int doRemap, int inSel, int outSel) {
    __shared__ float sv[NMAX];
    __shared__ int   si[NMAX];
    int b = blockIdx.x, t = threadIdx.x;
    float inv = d_norms[layer];

    for (int i = t; i < NMAX; i += 512) {
        sv[i] = (i < n) ? d_score[b * NMAX + i] * inv : -FLT_MAX;
        si[i] = i;
        d_score[b * NMAX + i] = 0.f;
    }
    __syncthreads();

    for (int size = 2; size <= NMAX; size <<= 1) {
        for (int stride = size >> 1; stride > 0; stride >>= 1) {
            for (int i = t; i < NMAX; i += 512) {
                int j = i ^ stride;
                if (j > i) {
                    float v1 = sv[i], v2 = sv[j];
                    int   i1 = si[i], i2 = si[j];
                    bool gt = (v1 > v2) || (v1 == v2 && i1 < i2);
                    bool up = ((i & size) == 0);
                    if (up ? gt : !gt) {
                        sv[i] = v2; sv[j] = v1;
                        si[i] = i2; si[j] = i1;
                    }
                }
            }
            __syncthreads();
        }
    }

    for (int i = t; i < NMAX; i += 512) d_newidx[b * NMAX + i] = -1;
    __syncthreads();
    for (int j = t; j < k; j += 512) {
        int   src = si[NMAX - 1 - j];
        float val = sv[NMAX - 1 - j];
        d_perm [b * NMAX + j]    = src;
        d_tanhv[b * NMAX + j]    = tanhf(val);
        d_newidx[b * NMAX + src] = j;
    }

    if (doRemap) {
        __syncthreads();
        const int* S = esrc(inSel) + b * EMAX;
        const int* D = edst(inSel) + b * EMAX;
        int* So = esrc_w(outSel) + b * EMAX;
        int* Do = edst_w(outSel) + b * EMAX;
        for (int e = t; e < EMAX; e += 512) {
            int s = S[e], d = D[e];
            int s2 = -1, d2 = 0;
            if (s >= 0) {
                s2 = d_newidx[b * NMAX + s];
                d2 = d_newidx[b * NMAX + d];
                if (d2 < 0) s2 = -1;
                if (d2 < 0) d2 = 0;
            }
            So[e] = s2;
            Do[e] = (s2 >= 0) ? d2 : 0;
        }
    }
}

// ---------------------------------------------------------------------------
// Gather (layers 0,1 only): xb fp16 planes = split(hb[perm]*tanh)
// ---------------------------------------------------------------------------
__global__ void __launch_bounds__(128) gather_kernel(int k) {
    int b = blockIdx.y, j = blockIdx.x;
    if (j >= k) return;
    int t = threadIdx.x;
    int   p  = d_perm [b * NMAX + j];
    float tv = d_tanhv[b * NMAX + j];
    float4 v = ((const float4*)(d_hb + (size_t)(b * NMAX + p) * DIM))[t];
    v.x *= tv; v.y *= tv; v.z *= tv; v.w *= tv;
    uint2 h, l;
    split4h(v, h, l);
    ((uint2*)(d_xbh + (size_t)(b * NMAX + j) * DIM))[t] = h;
    ((uint2*)(d_xbl + (size_t)(b * NMAX + j) * DIM))[t] = l;
}

// ---------------------------------------------------------------------------
// Readout phase 1: partial max/sum over a j-chunk of the k kept nodes.
// grid (2 f-chunks, RJC j-chunks, BATCH); 256 threads.
// ---------------------------------------------------------------------------
__global__ void __launch_bounds__(256) readout_part_kernel(int k) {
    int b  = blockIdx.z;
    int jc = blockIdx.y;
    int f  = blockIdx.x * 256 + threadIdx.x;
    int j0 = jc * ((k + RJC - 1) / RJC);
    int j1 = min(k, j0 + (k + RJC - 1) / RJC);

    const float* H  = d_hb + (size_t)b * NMAX * DIM + f;
    const int*   P  = d_perm  + b * NMAX;
    const float* Tv = d_tanhv + b * NMAX;
    float mx = -FLT_MAX, sm = 0.f;
#pragma unroll 4
    for (int j = j0; j < j1; j++) {
        float v = H[(size_t)P[j] * DIM] * Tv[j];
        mx = fmaxf(mx, v);
        sm += v;
    }
    d_rmax[(jc * BATCH + b) * DIM + f] = mx;
    d_rsum[(jc * BATCH + b) * DIM + f] = sm;
}

// ---------------------------------------------------------------------------
// Readout phase 2: combine partials into d_z. grid (2, BATCH); 256 threads.
// ---------------------------------------------------------------------------
__global__ void __launch_bounds__(256) readout_comb_kernel(int k, int first) {
    int b = blockIdx.y;
    int f = blockIdx.x * 256 + threadIdx.x;
    float mx = -FLT_MAX, sm = 0.f;
#pragma unroll
    for (int jc = 0; jc < RJC; jc++) {
        mx = fmaxf(mx, d_rmax[(jc * BATCH + b) * DIM + f]);
        sm += d_rsum[(jc * BATCH + b) * DIM + f];
    }
    float mean = sm / (float)k;
    if (first) {
        d_z[b * 2 * DIM + f]       = mx;
        d_z[b * 2 * DIM + DIM + f] = mean;
    } else {
        d_z[b * 2 * DIM + f]       += mx;
        d_z[b * 2 * DIM + DIM + f] += mean;
    }
}

// ---------------------------------------------------------------------------
// Final MLP: out = relu(z @ lin1^T + b1) @ lin2^T + b2
// ---------------------------------------------------------------------------
__global__ void __launch_bounds__(256) mlp_kernel(
    const float* __restrict__ lin1W, const float* __restrict__ lin1b,
    const float* __restrict__ lin2W, const float* __restrict__ lin2b,
    float* __restrict__ out)
{
    int b = blockIdx.x, t = threadIdx.x;
    int warp = t >> 5, lane = t & 31;
    __shared__ float zsh[2 * DIM];
    __shared__ float y1[DIM];

    for (int i = t; i < 2 * DIM; i += 256) zsh[i] = d_z[b * 2 * DIM + i];
    __syncthreads();

    for (int o = warp * 64; o < warp * 64 + 64; o++) {
        const float* wr = lin1W + (size_t)o * 2 * DIM;
        float s = 0.f;
        for (int j = lane; j < 2 * DIM; j += 32) s = fmaf(zsh[j], wr[j], s);
#pragma unroll
        for (int off = 16; off > 0; off >>= 1) s += __shfl_xor_sync(0xffffffffu, s, off);
        if (lane == 0) y1[o] = fmaxf(s + lin1b[o], 0.f);
    }
    __syncthreads();

    for (int o = warp * 32; o < warp * 32 + 32; o++) {
        const float* wr = lin2W + (size_t)o * DIM;
        float s = 0.f;
        for (int j = lane; j < DIM; j += 32) s = fmaf(y1[j], wr[j], s);
#pragma unroll
        for (int off = 16; off > 0; off >>= 1) s += __shfl_xor_sync(0xffffffffu, s, off);
        if (lane == 0) out[b * 256 + o] = s + lin2b[o];
    }
}

// ---------------------------------------------------------------------------
// Host launcher
// ---------------------------------------------------------------------------
extern "C" void kernel_launch(void* const* d_in, const int* in_sizes, int n_in,
                              void* d_out, int out_size)
{
    const float* x       = (const float*)d_in[0];
    const int*   ei      = (const int*)  d_in[1];
    const float* c_lin_W = (const float*)d_in[2];
    const float* c_lin_b = (const float*)d_in[3];
    const float* c_upd_W = (const float*)d_in[4];
    const float* pool_w  = (const float*)d_in[5];
    const float* lin1_W  = (const float*)d_in[6];
    const float* lin1_b  = (const float*)d_in[7];
    const float* lin2_W  = (const float*)d_in[8];
    const float* lin2_b  = (const float*)d_in[9];
    float* out = (float*)d_out;

    cudaFuncSetAttribute(gemm_h3_kernel,
                         cudaFuncAttributeMaxDynamicSharedMemorySize, GSMEM_BYTES);

    const int ns[3] = {1024, 820, 656};
    const int ks[3] = {820, 656, 525};

    init_edges_kernel<<<dim3(EMAX / 256, BATCH), 256>>>(ei);
    zero_score_kernel<<<(BATCH * NMAX + 255) / 256, 256>>>();
    norms_kernel<<<3, 256>>>(pool_w);

    {
        int nx = BATCH * NMAX * DIM / 4;
        split_kernel<<<(nx + 255) / 256, 256>>>(x, 0, nx);
        int nl = 3 * DIM * DIM / 4;
        split_kernel<<<(nl + 255) / 256, 256>>>(c_lin_W, 1, nl);
        int nu = 3 * DIM * 2 * DIM / 4;
        split_kernel<<<(nu + 255) / 256, 256>>>(c_upd_W, 2, nu);
    }

    for (int l = 0; l < 3; l++) {
        int n = ns[l], k = ks[l];
        int inSel = l & 1;
        int outSel = inSel ^ 1;
        int xsel = (l == 0) ? 0 : 1;
        int nrow = (n + 127) / 128;

        // h = relu(x @ Wl^T + bl)
        gemm_h3_kernel<<<dim3(DIM / 128, nrow, BATCH), 256, GSMEM_BYTES>>>(
            xsel, l, c_lin_b + l * DIM, nullptr, n);

        build_csr_kernel<<<BATCH, 1024>>>(inSel);

        agg_split_kernel<<<dim3(n, BATCH), 128>>>(n);

        // x_new = relu([agg|x] @ Wu^T)  (+ fused raw score partials)
        gemm_h3_kernel<<<dim3(DIM / 128, nrow, BATCH), 256, GSMEM_BYTES>>>(
            2 + xsel, l, nullptr, pool_w + l * DIM, n);

        // top-k (+ tanh, newidx) + fused edge remap
        topk_kernel<<<BATCH, 512>>>(n, k, l, l < 2 ? 1 : 0, inSel, outSel);

        if (l < 2)
            gather_kernel<<<dim3(k, BATCH), 128>>>(k);

        // parallel readout: partials then combine
        readout_part_kernel<<<dim3(DIM / 256, RJC, BATCH), 256>>>(k);
        readout_comb_kernel<<<dim3(DIM / 256, BATCH), 256>>>(k, l == 0 ? 1 : 0);
    }

    mlp_kernel<<<BATCH, 256>>>(lin1_W, lin1_b, lin2_W, lin2_b, out);
}

// round 15
// speedup vs baseline: 1.3458x; 1.0516x over previous
#include <cuda_runtime.h>
#include <cuda_fp16.h>
#include <cfloat>
#include <math.h>
#include <stdint.h>

// ---------------------------------------------------------------------------
// Problem constants
// ---------------------------------------------------------------------------
#define BATCH 16
#define NMAX  1024
#define EMAX  16384
#define DIM   512
// ns = {1024, 820, 656}, ks = {820, 656, 525}

// ---------------------------------------------------------------------------
// Device scratch (static; no cudaMalloc allowed)
// ---------------------------------------------------------------------------
__device__ float d_hbA[BATCH * NMAX * DIM];     // gemm1 outputs (h)
__device__ float d_hbB[BATCH * NMAX * DIM];     // gemm2 outputs (x_new)

// fp16 hi/lo operand planes (row-major, K contiguous, stride DIM)
__device__ __half d_x0h[BATCH * NMAX * DIM];    // input x split
__device__ __half d_x0l[BATCH * NMAX * DIM];
__device__ __half d_xbh[BATCH * NMAX * DIM];    // pooled split
__device__ __half d_xbl[BATCH * NMAX * DIM];
__device__ __half d_agh[BATCH * NMAX * DIM];    // aggregated split
__device__ __half d_agl[BATCH * NMAX * DIM];

__device__ __half d_wlh[3 * DIM * DIM];         // c_lin_W split
__device__ __half d_wll[3 * DIM * DIM];
__device__ __half d_wuh[3 * DIM * 2 * DIM];     // c_upd_W split
__device__ __half d_wul[3 * DIM * 2 * DIM];

__device__ int   d_srcA[BATCH * EMAX];
__device__ int   d_dstA[BATCH * EMAX];
__device__ int   d_srcB[BATCH * EMAX];
__device__ int   d_dstB[BATCH * EMAX];

__device__ int   d_off [BATCH * (NMAX + 1)];
__device__ int   d_csr [BATCH * EMAX];

__device__ float d_score[BATCH * NMAX];
__device__ int   d_perm [BATCH * NMAX];
__device__ float d_tanhv[BATCH * NMAX];
__device__ int   d_newidx[BATCH * NMAX];

// readout partials: [jchunk][batch][512] for max and sum
#define RJC 8
__device__ float d_rmax[RJC * BATCH * DIM];
__device__ float d_rsum[RJC * BATCH * DIM];

__device__ float d_z[BATCH * 2 * DIM];
__device__ float d_norms[4];

__device__ __forceinline__ const int* esrc(int sel) { return sel ? d_srcB : d_srcA; }
__device__ __forceinline__ const int* edst(int sel) { return sel ? d_dstB : d_dstA; }
__device__ __forceinline__ int* esrc_w(int sel) { return sel ? d_srcB : d_srcA; }
__device__ __forceinline__ int* edst_w(int sel) { return sel ? d_dstB : d_dstA; }

// ---------------------------------------------------------------------------
// fp16 helpers
// ---------------------------------------------------------------------------
__device__ __forceinline__ void split4h(float4 v, uint2& h, uint2& l) {
    __half hx = __float2half(v.x), hy = __float2half(v.y);
    __half hz = __float2half(v.z), hw = __float2half(v.w);
    __half lx = __float2half(v.x - __half2float(hx));
    __half ly = __float2half(v.y - __half2float(hy));
    __half lz = __float2half(v.z - __half2float(hz));
    __half lw = __float2half(v.w - __half2float(hw));
    h.x = ((uint32_t)__half_as_ushort(hy) << 16) | __half_as_ushort(hx);
    h.y = ((uint32_t)__half_as_ushort(hw) << 16) | __half_as_ushort(hz);
    l.x = ((uint32_t)__half_as_ushort(ly) << 16) | __half_as_ushort(lx);
    l.y = ((uint32_t)__half_as_ushort(lw) << 16) | __half_as_ushort(lz);
}

__device__ __forceinline__ void mma_h16(float* c, const uint32_t* a, const uint32_t* b) {
    asm volatile(
        "mma.sync.aligned.m16n8k16.row.col.f32.f16.f16.f32 "
        "{%0,%1,%2,%3}, {%4,%5,%6,%7}, {%8,%9}, {%0,%1,%2,%3};"
        : "+f"(c[0]), "+f"(c[1]), "+f"(c[2]), "+f"(c[3])
        : "r"(a[0]), "r"(a[1]), "r"(a[2]), "r"(a[3]), "r"(b[0]), "r"(b[1]));
}

__device__ __forceinline__ void ldsm4(uint32_t* r, uint32_t a) {
    asm volatile("ldmatrix.sync.aligned.m8n8.x4.shared.b16 {%0,%1,%2,%3}, [%4];"
                 : "=r"(r[0]), "=r"(r[1]), "=r"(r[2]), "=r"(r[3]) : "r"(a));
}

__device__ __forceinline__ void cpasync16(uint32_t dst, const void* src, int szbytes) {
    asm volatile("cp.async.cg.shared.global [%0], [%1], 16, %2;"
                 :: "r"(dst), "l"(src), "r"(szbytes));
}
__device__ __forceinline__ void cpasync_commit() {
    asm volatile("cp.async.commit_group;");
}
template <int N>
__device__ __forceinline__ void cpasync_wait() {
    asm volatile("cp.async.wait_group %0;" :: "n"(N));
}

// ---------------------------------------------------------------------------
// Init / split kernels
// ---------------------------------------------------------------------------
__global__ void init_edges_kernel(const int* __restrict__ ei) {
    int b = blockIdx.y;
    int e = blockIdx.x * blockDim.x + threadIdx.x;
    if (e < EMAX) {
        d_srcA[b * EMAX + e] = ei[(size_t)b * 2 * EMAX + e];
        d_dstA[b * EMAX + e] = ei[(size_t)b * 2 * EMAX + EMAX + e];
    }
}

__global__ void zero_score_kernel() {
    int i = blockIdx.x * blockDim.x + threadIdx.x;
    if (i < BATCH * NMAX) d_score[i] = 0.f;
}

__global__ void norms_kernel(const float* __restrict__ pw) {
    int l = blockIdx.x;
    int t = threadIdx.x;
    __shared__ float red[256];
    float s = 0.f;
    for (int j = t; j < DIM; j += 256) {
        float v = pw[l * DIM + j];
        s = fmaf(v, v, s);
    }
    red[t] = s;
    __syncthreads();
    for (int o = 128; o > 0; o >>= 1) {
        if (t < o) red[t] += red[t + o];
        __syncthreads();
    }
    if (t == 0) d_norms[l] = 1.0f / sqrtf(red[0]);
}

// dsel: 0 -> x0, 1 -> wl, 2 -> wu   (flat elementwise, float4 granules)
__global__ void split_kernel(const float* __restrict__ src, int dsel, int n4) {
    int i = blockIdx.x * blockDim.x + threadIdx.x;
    if (i >= n4) return;
    __half* H = (dsel == 0) ? d_x0h : (dsel == 1) ? d_wlh : d_wuh;
    __half* L = (dsel == 0) ? d_x0l : (dsel == 1) ? d_wll : d_wul;
    float4 v = ((const float4*)src)[i];
    uint2 h, l;
    split4h(v, h, l);
    ((uint2*)H)[i] = h;
    ((uint2*)L)[i] = l;
}

// ---------------------------------------------------------------------------
// 3xFP16 tensor-core GEMM (BM=128 BN=128 BK=16, 3-stage, ldmatrix)
//   C[M,512] = act(A[M,K] @ W[512,K]^T + bias),  C = csel ? hbB : hbA
//   If pw != nullptr: fused score partials into d_score.
//   asel: 0 A=x0 (K=512), 1 A=xb (K=512), 2 A=[agg|x0] (K=1024), 3 A=[agg|xb]
// ---------------------------------------------------------------------------
#define PITCH_H 24
#define TILE_H  (128 * PITCH_H)
#define TILE_B  (TILE_H * 2)
#define GSMEM_BYTES (4 * 3 * TILE_B)   // 73728

__global__ void __launch_bounds__(256, 2) gemm_h3_kernel(
    int asel, int csel, int layer,
    const float* __restrict__ bias,
    const float* __restrict__ pw,
    int M)
{
    extern __shared__ __align__(16) __half gsm[];
    __half* AsH = gsm;
    __half* AsL = gsm + 3 * TILE_H;
    __half* BsH = gsm + 6 * TILE_H;
    __half* BsL = gsm + 9 * TILE_H;

    const int b  = blockIdx.z;
    const int Kw = (asel >= 2) ? (2 * DIM) : DIM;
    const int nch = Kw >> 4;

    const __half* AxH = ((asel == 0 || asel == 2) ? d_x0h : d_xbh) + (size_t)b * NMAX * DIM;
    const __half* AxL = ((asel == 0 || asel == 2) ? d_x0l : d_xbl) + (size_t)b * NMAX * DIM;
    const __half* AgH = d_agh + (size_t)b * NMAX * DIM;
    const __half* AgL = d_agl + (size_t)b * NMAX * DIM;
    const __half* Wh = (asel >= 2) ? (d_wuh + (size_t)layer * DIM * 2 * DIM)
                                   : (d_wlh + (size_t)layer * DIM * DIM);
    const __half* Wl = (asel >= 2) ? (d_wul + (size_t)layer * DIM * 2 * DIM)
                                   : (d_wll + (size_t)layer * DIM * DIM);
    float* C = (csel ? d_hbB : d_hbA) + (size_t)b * NMAX * DIM;

    const int tid  = threadIdx.x;
    const int brow = blockIdx.y * 128;
    const int bcol = blockIdx.x * 128;

    const int warp = tid >> 5;
    const int lane = tid & 31;
    const int wm   = warp & 1;
    const int wn   = warp >> 1;
    const int quad = lane >> 2;
    const int tq   = lane & 3;

    const int lr = tid >> 1;
    const int hh = (tid & 1) * 8;
    int arow = brow + lr; if (arow >= M) arow = M - 1;
    const int avalid = (brow + lr) < M ? 16 : 0;

    const uint32_t baseAh = (uint32_t)__cvta_generic_to_shared(AsH);
    const uint32_t baseAl = (uint32_t)__cvta_generic_to_shared(AsL);
    const uint32_t baseBh = (uint32_t)__cvta_generic_to_shared(BsH);
    const uint32_t baseBl = (uint32_t)__cvta_generic_to_shared(BsL);
    const uint32_t offCp = (uint32_t)(lr * PITCH_H + hh) * 2;

    const int lr8 = lane & 7, g = lane >> 3;
    const uint32_t oA = (uint32_t)((wm * 64 + (g & 1) * 8 + lr8) * PITCH_H + (g >> 1) * 8) * 2;
    const uint32_t oB = (uint32_t)((wn * 32 + (g >> 1) * 8 + lr8) * PITCH_H + (g & 1) * 8) * 2;

    float acc[4][4][4];
#pragma unroll
    for (int i = 0; i < 4; i++)
#pragma unroll
        for (int j = 0; j < 4; j++)
#pragma unroll
            for (int e = 0; e < 4; e++) acc[i][j][e] = 0.f;

    auto cp_chunk = [&](int c, int stage) {
        const int k0 = c << 4;
        const __half* aH; const __half* aL; int ko = k0;
        if (asel < 2 || k0 < DIM) {
            if (asel >= 2) { aH = AgH; aL = AgL; }
            else           { aH = AxH; aL = AxL; }
        } else {
            aH = AxH; aL = AxL; ko = k0 - DIM;
        }
        const uint32_t sb = (uint32_t)(stage * TILE_B) + offCp;
        cpasync16(baseAh + sb, aH + (size_t)arow * DIM + ko + hh, avalid);
        cpasync16(baseAl + sb, aL + (size_t)arow * DIM + ko + hh, avalid);
        cpasync16(baseBh + sb, Wh + (size_t)(bcol + lr) * Kw + k0 + hh, 16);
        cpasync16(baseBl + sb, Wl + (size_t)(bcol + lr) * Kw + k0 + hh, 16);
        cpasync_commit();
    };

    cp_chunk(0, 0);
    cp_chunk(1, 1);

    for (int c = 0; c < nch; c++) {
        if (c == nch - 1) cpasync_wait<0>();
        else              cpasync_wait<1>();
        __syncthreads();
        if (c + 2 < nch) cp_chunk(c + 2, (c + 2) % 3);

        const uint32_t sb = (uint32_t)((c % 3) * TILE_B);

        uint32_t ah[4][4], al[4][4];
#pragma unroll
        for (int mi = 0; mi < 4; mi++) {
            ldsm4(ah[mi], baseAh + sb + oA + mi * (16 * PITCH_H * 2));
            ldsm4(al[mi], baseAl + sb + oA + mi * (16 * PITCH_H * 2));
        }
        uint32_t bh[4][2], bl[4][2];
        ldsm4(&bh[0][0], baseBh + sb + oB);
        ldsm4(&bh[2][0], baseBh + sb + oB + 16 * PITCH_H * 2);
        ldsm4(&bl[0][0], baseBl + sb + oB);
        ldsm4(&bl[2][0], baseBl + sb + oB + 16 * PITCH_H * 2);

#pragma unroll
        for (int mi = 0; mi < 4; mi++)
#pragma unroll
            for (int ni = 0; ni < 4; ni++) {
                mma_h16(acc[mi][ni], al[mi], bh[ni]);
                mma_h16(acc[mi][ni], ah[mi], bl[ni]);
                mma_h16(acc[mi][ni], ah[mi], bh[ni]);
            }
    }

    // epilogue: bias + relu (+ fused score partials)
    float wv[4][2];
    if (pw) {
#pragma unroll
        for (int ni = 0; ni < 4; ni++) {
            const int c0 = bcol + wn * 32 + ni * 8 + 2 * tq;
            wv[ni][0] = pw[c0];
            wv[ni][1] = pw[c0 + 1];
        }
    }

#pragma unroll
    for (int mi = 0; mi < 4; mi++) {
        const int r0 = brow + wm * 64 + mi * 16 + quad;
        float sc0 = 0.f, sc1 = 0.f;
#pragma unroll
        for (int ni = 0; ni < 4; ni++) {
            const int c0 = bcol + wn * 32 + ni * 8 + 2 * tq;
            float bv0 = 0.f, bv1 = 0.f;
            if (bias) { bv0 = bias[c0]; bv1 = bias[c0 + 1]; }
            float v0x = fmaxf(acc[mi][ni][0] + bv0, 0.f);
            float v0y = fmaxf(acc[mi][ni][1] + bv1, 0.f);
            float v1x = fmaxf(acc[mi][ni][2] + bv0, 0.f);
            float v1y = fmaxf(acc[mi][ni][3] + bv1, 0.f);
            if (r0 < M)     *(float2*)(C + (size_t)r0 * DIM + c0) = make_float2(v0x, v0y);
            if (r0 + 8 < M) *(float2*)(C + (size_t)(r0 + 8) * DIM + c0) = make_float2(v1x, v1y);
            if (pw) {
                sc0 = fmaf(v0x, wv[ni][0], fmaf(v0y, wv[ni][1], sc0));
                sc1 = fmaf(v1x, wv[ni][0], fmaf(v1y, wv[ni][1], sc1));
            }
        }
        if (pw) {
            sc0 += __shfl_xor_sync(0xffffffffu, sc0, 1);
            sc0 += __shfl_xor_sync(0xffffffffu, sc0, 2);
            sc1 += __shfl_xor_sync(0xffffffffu, sc1, 1);
            sc1 += __shfl_xor_sync(0xffffffffu, sc1, 2);
            if (tq == 0) {
                if (r0 < M)     atomicAdd(&d_score[b * NMAX + r0], sc0);
                if (r0 + 8 < M) atomicAdd(&d_score[b * NMAX + r0 + 8], sc1);
            }
        }
    }
}

// ---------------------------------------------------------------------------
// Fused CSR build
// ---------------------------------------------------------------------------
__global__ void __launch_bounds__(1024) build_csr_kernel(int sel) {
    __shared__ int sh[NMAX];
    __shared__ int cur[NMAX];
    const int b = blockIdx.x, t = threadIdx.x;

    sh[t] = 0;
    __syncthreads();

    const int* S = esrc(sel) + b * EMAX;
    const int* D = edst(sel) + b * EMAX;

#pragma unroll 4
    for (int e = t; e < EMAX; e += 1024) {
        int s = S[e], d = D[e];
        if (s >= 0 && s != d) atomicAdd(&sh[d], 1);
    }
    __syncthreads();

    int v = sh[t];
    for (int off = 1; off < NMAX; off <<= 1) {
        int add = (t >= off) ? sh[t - off] : 0;
        __syncthreads();
        sh[t] += add;
        __syncthreads();
    }
    int excl = sh[t] - v;
    d_off[b * (NMAX + 1) + t] = excl;
    cur[t] = excl;
    if (t == NMAX - 1) d_off[b * (NMAX + 1) + NMAX] = sh[t];
    __syncthreads();

#pragma unroll 4
    for (int e = t; e < EMAX; e += 1024) {
        int s = S[e], d = D[e];
        if (s >= 0 && s != d) {
            int pos = atomicAdd(&cur[d], 1);
            d_csr[b * EMAX + pos] = s;
        }
    }
}

// ---------------------------------------------------------------------------
// Aggregation: agg[i] = h[i] + sum_{j->i} h[j] (h in hbA), split to fp16.
// ---------------------------------------------------------------------------
__global__ void __launch_bounds__(128) agg_split_kernel(int n) {
    int b = blockIdx.y, i = blockIdx.x;
    if (i >= n) return;
    int t = threadIdx.x;
    size_t row = (size_t)(b * NMAX + i);

    float4 acc = ((const float4*)(d_hbA + row * DIM))[t];
    float4 acc2 = make_float4(0.f, 0.f, 0.f, 0.f);
    int beg = d_off[b * (NMAX + 1) + i];
    int end = d_off[b * (NMAX + 1) + i + 1];
    int e = beg;
    for (; e + 1 < end; e += 2) {
        int s0 = d_csr[b * EMAX + e];
        int s1 = d_csr[b * EMAX + e + 1];
        float4 v0 = ((const float4*)(d_hbA + (size_t)(b * NMAX + s0) * DIM))[t];
        float4 v1 = ((const float4*)(d_hbA + (size_t)(b * NMAX + s1) * DIM))[t];
        acc.x += v0.x; acc.y += v0.y; acc.z += v0.z; acc.w += v0.w;
        acc2.x += v1.x; acc2.y += v1.y; acc2.z += v1.z; acc2.w += v1.w;
    }
    if (e < end) {
        int s0 = d_csr[b * EMAX + e];
        float4 v0 = ((const float4*)(d_hbA + (size_t)(b * NMAX + s0) * DIM))[t];
        acc.x += v0.x; acc.y += v0.y; acc.z += v0.z; acc.w += v0.w;
    }
    acc.x += acc2.x; acc.y += acc2.y; acc.z += acc2.z; acc.w += acc2.w;

    uint2 h, l;
    split4h(acc, h, l);
    ((uint2*)(d_agh + row * DIM))[t] = h;
    ((uint2*)(d_agl + row * DIM))[t] = l;
}

// ---------------------------------------------------------------------------
// Top-k via bitonic sort (tie-break: lower index wins) + fused edge remap.
// ---------------------------------------------------------------------------
__global__ void __launch_bounds__(512) topk_kernel(int n, int k, int layer,
                                                   int doRemap, int inSel, int outSel) {
    __shared__ float sv[NMAX];
    __shared__ int   si[NMAX];
    int b = blockIdx.x, t = threadIdx.x;
    float inv = d_norms[layer];

    for (int i = t; i < NMAX; i += 512) {
        sv[i] = (i < n) ? d_score[b * NMAX + i] * inv : -FLT_MAX;
        si[i] = i;
        d_score[b * NMAX + i] = 0.f;
    }
    __syncthreads();

    for (int size = 2; size <= NMAX; size <<= 1) {
        for (int stride = size >> 1; stride > 0; stride >>= 1) {
            for (int i = t; i < NMAX; i += 512) {
                int j = i ^ stride;
                if (j > i) {
                    float v1 = sv[i], v2 = sv[j];
                    int   i1 = si[i], i2 = si[j];
                    bool gt = (v1 > v2) || (v1 == v2 && i1 < i2);
                    bool up = ((i & size) == 0);
                    if (up ? gt : !gt) {
                        sv[i] = v2; sv[j] = v1;
                        si[i] = i2; si[j] = i1;
                    }
                }
            }
            __syncthreads();
        }
    }

    for (int i = t; i < NMAX; i += 512) d_newidx[b * NMAX + i] = -1;
    __syncthreads();
    for (int j = t; j < k; j += 512) {
        int   src = si[NMAX - 1 - j];
        float val = sv[NMAX - 1 - j];
        d_perm [b * NMAX + j]    = src;
        d_tanhv[b * NMAX + j]    = tanhf(val);
        d_newidx[b * NMAX + src] = j;
    }

    if (doRemap) {
        __syncthreads();
        const int* S = esrc(inSel) + b * EMAX;
        const int* D = edst(inSel) + b * EMAX;
        int* So = esrc_w(outSel) + b * EMAX;
        int* Do = edst_w(outSel) + b * EMAX;
        for (int e = t; e < EMAX; e += 512) {
            int s = S[e], d = D[e];
            int s2 = -1, d2 = 0;
            if (s >= 0) {
                s2 = d_newidx[b * NMAX + s];
                d2 = d_newidx[b * NMAX + d];
                if (d2 < 0) s2 = -1;
                if (d2 < 0) d2 = 0;
            }
            So[e] = s2;
            Do[e] = (s2 >= 0) ? d2 : 0;
        }
    }
}

// ---------------------------------------------------------------------------
// Gather (layers 0,1): xb fp16 planes = split(hbB[perm]*tanh)
// ---------------------------------------------------------------------------
__global__ void __launch_bounds__(128) gather_kernel(int k) {
    int b = blockIdx.y, j = blockIdx.x;
    if (j >= k) return;
    int t = threadIdx.x;
    int   p  = d_perm [b * NMAX + j];
    float tv = d_tanhv[b * NMAX + j];
    float4 v = ((const float4*)(d_hbB + (size_t)(b * NMAX + p) * DIM))[t];
    v.x *= tv; v.y *= tv; v.z *= tv; v.w *= tv;
    uint2 h, l;
    split4h(v, h, l);
    ((uint2*)(d_xbh + (size_t)(b * NMAX + j) * DIM))[t] = h;
    ((uint2*)(d_xbl + (size_t)(b * NMAX + j) * DIM))[t] = l;
}

// ---------------------------------------------------------------------------
// Readout phase 1: partial max/sum over a j-chunk of the k kept nodes (hbB).
// ---------------------------------------------------------------------------
__global__ void __launch_bounds__(256) readout_part_kernel(int k) {
    int b  = blockIdx.z;
    int jc = blockIdx.y;
    int f  = blockIdx.x * 256 + threadIdx.x;
    int j0 = jc * ((k + RJC - 1) / RJC);
    int j1 = min(k, j0 + (k + RJC - 1) / RJC);

    const float* H  = d_hbB + (size_t)b * NMAX * DIM + f;
    const int*   P  = d_perm  + b * NMAX;
    const float* Tv = d_tanhv + b * NMAX;
    float mx = -FLT_MAX, sm = 0.f;
#pragma unroll 4
    for (int j = j0; j < j1; j++) {
        float v = H[(size_t)P[j] * DIM] * Tv[j];
        mx = fmaxf(mx, v);
        sm += v;
    }
    d_rmax[(jc * BATCH + b) * DIM + f] = mx;
    d_rsum[(jc * BATCH + b) * DIM + f] = sm;
}

// ---------------------------------------------------------------------------
// Readout phase 2: combine partials into d_z.
// ---------------------------------------------------------------------------
__global__ void __launch_bounds__(256) readout_comb_kernel(int k, int first) {
    int b = blockIdx.y;
    int f = blockIdx.x * 256 + threadIdx.x;
    float mx = -FLT_MAX, sm = 0.f;
#pragma unroll
    for (int jc = 0; jc < RJC; jc++) {
        mx = fmaxf(mx, d_rmax[(jc * BATCH + b) * DIM + f]);
        sm += d_rsum[(jc * BATCH + b) * DIM + f];
    }
    float mean = sm / (float)k;
    if (first) {
        d_z[b * 2 * DIM + f]       = mx;
        d_z[b * 2 * DIM + DIM + f] = mean;
    } else {
        d_z[b * 2 * DIM + f]       += mx;
        d_z[b * 2 * DIM + DIM + f] += mean;
    }
}

// ---------------------------------------------------------------------------
// Final MLP: out = relu(z @ lin1^T + b1) @ lin2^T + b2
// ---------------------------------------------------------------------------
__global__ void __launch_bounds__(256) mlp_kernel(
    const float* __restrict__ lin1W, const float* __restrict__ lin1b,
    const float* __restrict__ lin2W, const float* __restrict__ lin2b,
    float* __restrict__ out)
{
    int b = blockIdx.x, t = threadIdx.x;
    int warp = t >> 5, lane = t & 31;
    __shared__ float zsh[2 * DIM];
    __shared__ float y1[DIM];

    for (int i = t; i < 2 * DIM; i += 256) zsh[i] = d_z[b * 2 * DIM + i];
    __syncthreads();

    for (int o = warp * 64; o < warp * 64 + 64; o++) {
        const float* wr = lin1W + (size_t)o * 2 * DIM;
        float s = 0.f;
        for (int j = lane; j < 2 * DIM; j += 32) s = fmaf(zsh[j], wr[j], s);
#pragma unroll
        for (int off = 16; off > 0; off >>= 1) s += __shfl_xor_sync(0xffffffffu, s, off);
        if (lane == 0) y1[o] = fmaxf(s + lin1b[o], 0.f);
    }
    __syncthreads();

    for (int o = warp * 32; o < warp * 32 + 32; o++) {
        const float* wr = lin2W + (size_t)o * DIM;
        float s = 0.f;
        for (int j = lane; j < DIM; j += 32) s = fmaf(y1[j], wr[j], s);
#pragma unroll
        for (int off = 16; off > 0; off >>= 1) s += __shfl_xor_sync(0xffffffffu, s, off);
        if (lane == 0) out[b * 256 + o] = s + lin2b[o];
    }
}

// ---------------------------------------------------------------------------
// Host launcher — kernel launches + capture-safe fork/join on a side stream.
// Streams/events created lazily on the FIRST (uncaptured) correctness call.
// ---------------------------------------------------------------------------
extern "C" void kernel_launch(void* const* d_in, const int* in_sizes, int n_in,
                              void* d_out, int out_size)
{
    const float* x       = (const float*)d_in[0];
    const int*   ei      = (const int*)  d_in[1];
    const float* c_lin_W = (const float*)d_in[2];
    const float* c_lin_b = (const float*)d_in[3];
    const float* c_upd_W = (const float*)d_in[4];
    const float* pool_w  = (const float*)d_in[5];
    const float* lin1_W  = (const float*)d_in[6];
    const float* lin1_b  = (const float*)d_in[7];
    const float* lin2_W  = (const float*)d_in[8];
    const float* lin2_b  = (const float*)d_in[9];
    float* out = (float*)d_out;

    static cudaStream_t sSide = nullptr;
    static cudaEvent_t  evF = nullptr, evJ = nullptr;
    static bool inited = false;
    if (!inited) {
        cudaStreamCreateWithFlags(&sSide, cudaStreamNonBlocking);
        cudaEventCreateWithFlags(&evF, cudaEventDisableTiming);
        cudaEventCreateWithFlags(&evJ, cudaEventDisableTiming);
        cudaFuncSetAttribute(gemm_h3_kernel,
                             cudaFuncAttributeMaxDynamicSharedMemorySize, GSMEM_BYTES);
        inited = true;
    }
    cudaStream_t s0 = 0;

    const int ns[3] = {1024, 820, 656};
    const int ks[3] = {820, 656, 525};

    // init phase (order keeps gemm_h3 as the 6th kernel launch for ncu)
    {
        int nx = BATCH * NMAX * DIM / 4;
        split_kernel<<<(nx + 255) / 256, 256>>>(x, 0, nx);              // 1
        int nl = 3 * DIM * DIM / 4;
        split_kernel<<<(nl + 255) / 256, 256>>>(c_lin_W, 1, nl);        // 2
        int nu = 3 * DIM * 2 * DIM / 4;
        split_kernel<<<(nu + 255) / 256, 256>>>(c_upd_W, 2, nu);        // 3
    }
    init_edges_kernel<<<dim3(EMAX / 256, BATCH), 256>>>(ei);            // 4
    zero_score_kernel<<<(BATCH * NMAX + 255) / 256, 256>>>();           // 5

    // fork: csr(l0) on side (depends on init_edges)
    cudaEventRecord(evF, s0);
    gemm_h3_kernel<<<dim3(DIM / 128, 8, BATCH), 256, GSMEM_BYTES, s0>>>(  // 6 <- ncu
        0, 0, 0, c_lin_b, nullptr, ns[0]);
    cudaStreamWaitEvent(sSide, evF, 0);
    build_csr_kernel<<<BATCH, 1024, 0, sSide>>>(0);                     // 7 (side)
    cudaEventRecord(evJ, sSide);
    norms_kernel<<<3, 256>>>(pool_w);                                   // 8

    for (int l = 0; l < 3; l++) {
        int n = ns[l], k = ks[l];
        int inSel = l & 1;
        int outSel = inSel ^ 1;
        int nrow = (n + 127) / 128;

        // join side (csr(l) [+ readout(l-1)]) before agg
        cudaStreamWaitEvent(s0, evJ, 0);
        agg_split_kernel<<<dim3(n, BATCH), 128, 0, s0>>>(n);

        // x_new = relu([agg|x] @ Wu^T) -> hbB (+ fused raw score partials)
        gemm_h3_kernel<<<dim3(DIM / 128, nrow, BATCH), 256, GSMEM_BYTES, s0>>>(
            2 + (l == 0 ? 0 : 1), 1, l, nullptr, pool_w + l * DIM, n);

        // top-k (+ tanh, newidx) + fused edge remap
        topk_kernel<<<BATCH, 512, 0, s0>>>(n, k, l, l < 2 ? 1 : 0, inSel, outSel);

        // fork after topk: readout (+ next csr) on side
        cudaEventRecord(evF, s0);
        cudaStreamWaitEvent(sSide, evF, 0);
        readout_part_kernel<<<dim3(DIM / 256, RJC, BATCH), 256, 0, sSide>>>(k);
        readout_comb_kernel<<<dim3(DIM / 256, BATCH), 256, 0, sSide>>>(k, l == 0 ? 1 : 0);
        if (l < 2)
            build_csr_kernel<<<BATCH, 1024, 0, sSide>>>(outSel);
        cudaEventRecord(evJ, sSide);

        if (l < 2) {
            // main: gather pooled features, then next layer's gemm1 -> hbA
            gather_kernel<<<dim3(k, BATCH), 128, 0, s0>>>(k);
            int nrow2 = (ks[l] + 127) / 128;
            gemm_h3_kernel<<<dim3(DIM / 128, nrow2, BATCH), 256, GSMEM_BYTES, s0>>>(
                1, 0, l + 1, c_lin_b + (l + 1) * DIM, nullptr, ks[l]);
        }
    }

    // join side (last readout) before the MLP
    cudaStreamWaitEvent(s0, evJ, 0);
    mlp_kernel<<<BATCH, 256, 0, s0>>>(lin1_W, lin1_b, lin2_W, lin2_b, out);
}